// round 1
// baseline (speedup 1.0000x reference)
#include <cuda_runtime.h>
#include <math.h>

#define S_TOT 2560      // B*N sequences
#define T_LEN 70
#define HIDN  200
#define G3    600       // 3*HIDN gate columns
#define IND   60        // input feature dim
#define NBAG  128
#define NSEN  20
#define NREL  100

// ---------------- scratch (static device memory; no allocation) -------------
__device__ float g_x[S_TOT * T_LEN * IND];                       // 43 MB
__device__ float g_xp_f[(size_t)T_LEN * S_TOT * G3];             // 430 MB
__device__ float g_xp_b[(size_t)T_LEN * S_TOT * G3];             // 430 MB
__device__ float g_seq_f[(size_t)T_LEN * S_TOT * HIDN];          // 143 MB
__device__ float g_seq_b[(size_t)T_LEN * S_TOT * HIDN];          // 143 MB
__device__ float g_h[2][2][S_TOT * HIDN];                        // dir x pingpong
__device__ float g_H[S_TOT * HIDN];                              // word-attn output
__device__ float g_bagloss[NBAG];

__device__ __forceinline__ float sigm(float x) { return 1.f / (1.f + expf(-x)); }

// ---------------- init hidden state to zero --------------------------------
__global__ void init_h_kernel() {
    int i = blockIdx.x * blockDim.x + threadIdx.x;
    if (i < S_TOT * HIDN) { g_h[0][0][i] = 0.f; g_h[1][0][i] = 0.f; }
}

// ---------------- embedding gather + concat --------------------------------
__global__ void gather_kernel(const int* __restrict__ tok, const int* __restrict__ p1,
                              const int* __restrict__ p2, const float* __restrict__ emb,
                              const float* __restrict__ pemb) {
    int idx = blockIdx.x * blockDim.x + threadIdx.x;
    if (idx >= S_TOT * T_LEN * IND) return;
    int st = idx / IND;
    int c  = idx - st * IND;
    float v;
    if (c < 50)      v = emb[(size_t)tok[st] * 50 + c];
    else if (c < 55) v = pemb[(size_t)p1[st] * 5 + (c - 50)];
    else             v = pemb[(size_t)p2[st] * 5 + (c - 55)];
    g_x[idx] = v;
}

// ---------------- xp = x @ W_ih^T + b_ih  (both directions) ----------------
// grid: (179200/64, 10, 2)   block: 256   tile: 64 rows x 64 cols, K=60
__global__ void __launch_bounds__(256) xp_gemm_kernel(
    const float* __restrict__ Wf, const float* __restrict__ Wb,
    const float* __restrict__ bf, const float* __restrict__ bb)
{
    const int dir = blockIdx.z;
    const float* W    = dir ? Wb : Wf;
    const float* bias = dir ? bb : bf;
    float* xp = dir ? g_xp_b : g_xp_f;

    const int m0 = blockIdx.x * 64;
    const int c0 = blockIdx.y * 64;

    __shared__ float As[IND][68];   // [k][row]
    __shared__ float Bs[IND][68];   // [k][col]

    for (int e = threadIdx.x; e < 64 * IND; e += 256) {
        int r = e / IND, k = e - r * IND;
        As[k][r] = g_x[(size_t)m0 * IND + e];            // contiguous global read
        int cc = c0 + r;
        Bs[k][r] = (cc < G3) ? W[(size_t)cc * IND + k] : 0.f;  // contiguous too
    }
    __syncthreads();

    const int tx = threadIdx.x & 15, ty = threadIdx.x >> 4;
    float acc[4][4] = {};
    #pragma unroll
    for (int k = 0; k < IND; k++) {
        float4 a = *(const float4*)&As[k][4 * ty];
        float4 b = *(const float4*)&Bs[k][4 * tx];
        float av[4] = {a.x, a.y, a.z, a.w};
        float bv[4] = {b.x, b.y, b.z, b.w};
        #pragma unroll
        for (int rr = 0; rr < 4; rr++)
            #pragma unroll
            for (int cc = 0; cc < 4; cc++)
                acc[rr][cc] += av[rr] * bv[cc];
    }

    #pragma unroll
    for (int rr = 0; rr < 4; rr++) {
        int m = m0 + 4 * ty + rr;
        int s = m / T_LEN, t = m - s * T_LEN;
        size_t base = ((size_t)t * S_TOT + s) * G3;
        #pragma unroll
        for (int cc = 0; cc < 4; cc++) {
            int c = c0 + 4 * tx + cc;
            if (c < G3) xp[base + c] = acc[rr][cc] + bias[c];
        }
    }
}

// ---------------- fused GRU step: gates GEMM + pointwise --------------------
// grid: (2560/64, ceil(200/32)=7, 2 dirs)  block: 256
// tile: 64 rows x 32 hidden units (3 gate accumulators each), K=200
__global__ void __launch_bounds__(256) gru_step_kernel(int step,
    const float* __restrict__ Whh_f, const float* __restrict__ Whh_b,
    const float* __restrict__ bhh_f, const float* __restrict__ bhh_b)
{
    const int dir = blockIdx.z;
    const int t = dir ? (T_LEN - 1 - step) : step;
    const float* W    = dir ? Whh_b : Whh_f;
    const float* bhh  = dir ? bhh_b : bhh_f;
    const float* hprev = g_h[dir][step & 1];
    float* hnext       = g_h[dir][(step + 1) & 1];
    const float* xp = (dir ? g_xp_b : g_xp_f) + (size_t)t * S_TOT * G3;
    float* seq      = (dir ? g_seq_b : g_seq_f) + (size_t)t * S_TOT * HIDN;

    const int row0 = blockIdx.x * 64;
    const int j0   = blockIdx.y * 32;

    __shared__ float As[16][68];    // [k][row]
    __shared__ float Bs[16][100];   // [k][gate*32 + h]

    const int tx = threadIdx.x & 15, ty = threadIdx.x >> 4;
    float acc[3][4][2] = {};

    for (int k0 = 0; k0 < HIDN; k0 += 16) {
        {   // A tile: 64 rows x 16 k, vectorized
            int r  = threadIdx.x >> 2;
            int kk = (threadIdx.x & 3) * 4;
            float4 a4 = make_float4(0.f, 0.f, 0.f, 0.f);
            if (k0 + kk < HIDN)
                a4 = *(const float4*)&hprev[(size_t)(row0 + r) * HIDN + k0 + kk];
            As[kk + 0][r] = a4.x; As[kk + 1][r] = a4.y;
            As[kk + 2][r] = a4.z; As[kk + 3][r] = a4.w;
        }
        #pragma unroll
        for (int l = 0; l < 6; l++) {   // B tile: 96 gate rows x 16 k
            int e    = threadIdx.x + l * 256;
            int gl   = e >> 4;          // 0..95
            int kk   = e & 15;
            int gate = gl >> 5;         // 0..2
            int h    = gl & 31;
            float v = 0.f;
            if (j0 + h < HIDN && k0 + kk < HIDN)
                v = W[(size_t)(gate * HIDN + j0 + h) * HIDN + k0 + kk];
            Bs[kk][gl] = v;
        }
        __syncthreads();
        #pragma unroll
        for (int k = 0; k < 16; k++) {
            float4 a  = *(const float4*)&As[k][4 * ty];
            float2 br = *(const float2*)&Bs[k][       2 * tx];
            float2 bz = *(const float2*)&Bs[k][32  +  2 * tx];
            float2 bn = *(const float2*)&Bs[k][64  +  2 * tx];
            float av[4] = {a.x, a.y, a.z, a.w};
            #pragma unroll
            for (int rr = 0; rr < 4; rr++) {
                acc[0][rr][0] += av[rr] * br.x;  acc[0][rr][1] += av[rr] * br.y;
                acc[1][rr][0] += av[rr] * bz.x;  acc[1][rr][1] += av[rr] * bz.y;
                acc[2][rr][0] += av[rr] * bn.x;  acc[2][rr][1] += av[rr] * bn.y;
            }
        }
        __syncthreads();
    }

    #pragma unroll
    for (int rr = 0; rr < 4; rr++) {
        int row = row0 + 4 * ty + rr;
        const float* xr = xp + (size_t)row * G3;
        #pragma unroll
        for (int hh = 0; hh < 2; hh++) {
            int j = j0 + 2 * tx + hh;
            if (j < HIDN) {
                float ghr = acc[0][rr][hh] + bhh[j];
                float ghz = acc[1][rr][hh] + bhh[HIDN + j];
                float ghn = acc[2][rr][hh] + bhh[2 * HIDN + j];
                float r = sigm(xr[j] + ghr);
                float z = sigm(xr[HIDN + j] + ghz);
                float n = tanhf(xr[2 * HIDN + j] + r * ghn);
                float hp = hprev[(size_t)row * HIDN + j];
                float hv = (1.f - z) * n + z * hp;
                hnext[(size_t)row * HIDN + j] = hv;
                seq[(size_t)row * HIDN + j]   = hv;
            }
        }
    }
}

// ---------------- word-level attention --------------------------------------
__global__ void __launch_bounds__(128) word_attn_kernel(const float* __restrict__ aw)
{
    const int s = blockIdx.x;
    __shared__ float sc[T_LEN];
    const int lane = threadIdx.x & 31, wid = threadIdx.x >> 5;

    for (int t = wid; t < T_LEN; t += 4) {
        const float* f = g_seq_f + ((size_t)t * S_TOT + s) * HIDN;
        const float* b = g_seq_b + ((size_t)t * S_TOT + s) * HIDN;
        float sum = 0.f;
        for (int d = lane; d < HIDN; d += 32)
            sum += tanhf(f[d] + b[d]) * aw[d];
        #pragma unroll
        for (int o = 16; o > 0; o >>= 1) sum += __shfl_xor_sync(0xffffffffu, sum, o);
        if (lane == 0) sc[t] = sum;
    }
    __syncthreads();
    if (threadIdx.x == 0) {
        float m = sc[0];
        for (int t = 1; t < T_LEN; t++) m = fmaxf(m, sc[t]);
        float ssum = 0.f;
        for (int t = 0; t < T_LEN; t++) { float e2 = expf(sc[t] - m); sc[t] = e2; ssum += e2; }
        float inv = 1.f / ssum;
        for (int t = 0; t < T_LEN; t++) sc[t] *= inv;
    }
    __syncthreads();
    for (int d = threadIdx.x; d < HIDN; d += 128) {
        float acc = 0.f;
        for (int t = 0; t < T_LEN; t++)
            acc += sc[t] * (g_seq_f[((size_t)t * S_TOT + s) * HIDN + d] +
                            g_seq_b[((size_t)t * S_TOT + s) * HIDN + d]);
        g_H[(size_t)s * HIDN + d] = acc;
    }
}

// ---------------- bag attention + logits + BCE ------------------------------
__global__ void __launch_bounds__(128) bag_kernel(
    const float* __restrict__ sen_a, const float* __restrict__ sen_r,
    const float* __restrict__ rel, const float* __restrict__ sen_d,
    const int* __restrict__ label, float* __restrict__ logits)
{
    const int b = blockIdx.x;
    __shared__ float Hs[NSEN][HIDN];
    __shared__ float ew[NSEN];
    __shared__ float Sv[HIDN];
    __shared__ float red[128];

    for (int e = threadIdx.x; e < NSEN * HIDN; e += 128)
        Hs[e / HIDN][e % HIDN] = g_H[(size_t)b * NSEN * HIDN + e];
    __syncthreads();

    const int lane = threadIdx.x & 31, wid = threadIdx.x >> 5;
    for (int n = wid; n < NSEN; n += 4) {
        float sum = 0.f;
        for (int d = lane; d < HIDN; d += 32)
            sum += Hs[n][d] * sen_a[d] * sen_r[d];
        #pragma unroll
        for (int o = 16; o > 0; o >>= 1) sum += __shfl_xor_sync(0xffffffffu, sum, o);
        if (lane == 0) ew[n] = sum;
    }
    __syncthreads();
    if (threadIdx.x == 0) {
        float m = ew[0];
        for (int n = 1; n < NSEN; n++) m = fmaxf(m, ew[n]);
        float s2 = 0.f;
        for (int n = 0; n < NSEN; n++) { float e2 = expf(ew[n] - m); ew[n] = e2; s2 += e2; }
        float inv = 1.f / s2;
        for (int n = 0; n < NSEN; n++) ew[n] *= inv;
    }
    __syncthreads();
    for (int d = threadIdx.x; d < HIDN; d += 128) {
        float acc = 0.f;
        for (int n = 0; n < NSEN; n++) acc += ew[n] * Hs[n][d];
        Sv[d] = acc;
    }
    __syncthreads();

    int lab = label[b];
    float bce = 0.f;
    if (threadIdx.x < NREL) {
        int r = threadIdx.x;
        float l = sen_d[r];
        for (int d = 0; d < HIDN; d++) l += Sv[d] * rel[(size_t)r * HIDN + d];
        logits[(size_t)b * NREL + r] = l;
        float tgt = (lab == r) ? 1.f : 0.f;
        bce = fmaxf(l, 0.f) - l * tgt + log1pf(expf(-fabsf(l)));
    }
    red[threadIdx.x] = bce;
    __syncthreads();
    for (int o = 64; o > 0; o >>= 1) {
        if (threadIdx.x < o) red[threadIdx.x] += red[threadIdx.x + o];
        __syncthreads();
    }
    if (threadIdx.x == 0) g_bagloss[b] = red[0] / (float)NREL;
}

__global__ void loss_sum_kernel(float* __restrict__ out) {
    __shared__ float red[128];
    red[threadIdx.x] = g_bagloss[threadIdx.x];
    __syncthreads();
    for (int o = 64; o > 0; o >>= 1) {
        if (threadIdx.x < o) red[threadIdx.x] += red[threadIdx.x + o];
        __syncthreads();
    }
    if (threadIdx.x == 0) out[0] = red[0];
}

// ---------------- launch ----------------------------------------------------
extern "C" void kernel_launch(void* const* d_in, const int* in_sizes, int n_in,
                              void* d_out, int out_size)
{
    const int*   tok    = (const int*)d_in[0];
    const int*   p1     = (const int*)d_in[1];
    const int*   p2     = (const int*)d_in[2];
    const int*   lab    = (const int*)d_in[3];
    const float* emb    = (const float*)d_in[4];
    const float* pemb   = (const float*)d_in[5];
    const float* Wih_f  = (const float*)d_in[6];
    const float* Whh_f  = (const float*)d_in[7];
    const float* bih_f  = (const float*)d_in[8];
    const float* bhh_f  = (const float*)d_in[9];
    const float* Wih_b  = (const float*)d_in[10];
    const float* Whh_b  = (const float*)d_in[11];
    const float* bih_b  = (const float*)d_in[12];
    const float* bhh_b  = (const float*)d_in[13];
    const float* aw     = (const float*)d_in[14];
    const float* sen_a  = (const float*)d_in[15];
    const float* sen_r  = (const float*)d_in[16];
    const float* rel    = (const float*)d_in[17];
    const float* sen_d  = (const float*)d_in[18];
    float* out = (float*)d_out;

    init_h_kernel<<<(S_TOT * HIDN + 255) / 256, 256>>>();
    gather_kernel<<<(S_TOT * T_LEN * IND + 255) / 256, 256>>>(tok, p1, p2, emb, pemb);

    dim3 g2(S_TOT * T_LEN / 64, (G3 + 63) / 64, 2);
    xp_gemm_kernel<<<g2, 256>>>(Wih_f, Wih_b, bih_f, bih_b);

    dim3 g3(S_TOT / 64, (HIDN + 31) / 32, 2);
    for (int step = 0; step < T_LEN; step++)
        gru_step_kernel<<<g3, 256>>>(step, Whh_f, Whh_b, bhh_f, bhh_b);

    word_attn_kernel<<<S_TOT, 128>>>(aw);
    bag_kernel<<<NBAG, 128>>>(sen_a, sen_r, rel, sen_d, lab, out + 1);
    loss_sum_kernel<<<1, 128>>>(out);
}

// round 2
// speedup vs baseline: 1.1190x; 1.1190x over previous
#include <cuda_runtime.h>
#include <math.h>

#define S_TOT 2560      // B*N sequences
#define T_LEN 70
#define HIDN  200
#define G3    600       // 3*HIDN gate columns
#define IND   60        // input feature dim
#define NBAG  128
#define NSEN  20
#define NREL  100

// ---------------- scratch (static device memory; no allocation) -------------
__device__ float g_x[S_TOT * T_LEN * IND];                       // 43 MB
__device__ float g_xp_f[(size_t)T_LEN * S_TOT * G3];             // 430 MB
__device__ float g_xp_b[(size_t)T_LEN * S_TOT * G3];             // 430 MB
__device__ float g_seq_f[(size_t)T_LEN * S_TOT * HIDN];          // 143 MB
__device__ float g_seq_b[(size_t)T_LEN * S_TOT * HIDN];          // 143 MB
__device__ float g_h[2][2][S_TOT * HIDN];                        // dir x pingpong
__device__ float g_H[S_TOT * HIDN];                              // word-attn output
__device__ float g_bagloss[NBAG];

__device__ __forceinline__ float sigm(float x) { return 1.f / (1.f + expf(-x)); }

// ---- packed f32x2 helpers (FFMA2: ptxas never emits it; HW has it) ---------
__device__ __forceinline__ unsigned long long pack2(float x, float y) {
    unsigned long long r;
    asm("mov.b64 %0, {%1, %2};" : "=l"(r) : "f"(x), "f"(y));
    return r;
}
__device__ __forceinline__ void ffma2(unsigned long long& d,
                                      unsigned long long a, unsigned long long b) {
    asm("fma.rn.f32x2 %0, %1, %2, %0;" : "+l"(d) : "l"(a), "l"(b));
}
__device__ __forceinline__ void unpack2(unsigned long long v, float& x, float& y) {
    asm("mov.b64 {%0, %1}, %2;" : "=f"(x), "=f"(y) : "l"(v));
}

// ---------------- init hidden state to zero --------------------------------
__global__ void init_h_kernel() {
    int i = blockIdx.x * blockDim.x + threadIdx.x;
    if (i < S_TOT * HIDN) { g_h[0][0][i] = 0.f; g_h[1][0][i] = 0.f; }
}

// ---------------- embedding gather + concat --------------------------------
__global__ void gather_kernel(const int* __restrict__ tok, const int* __restrict__ p1,
                              const int* __restrict__ p2, const float* __restrict__ emb,
                              const float* __restrict__ pemb) {
    int idx = blockIdx.x * blockDim.x + threadIdx.x;
    if (idx >= S_TOT * T_LEN * IND) return;
    int st = idx / IND;
    int c  = idx - st * IND;
    float v;
    if (c < 50)      v = emb[(size_t)tok[st] * 50 + c];
    else if (c < 55) v = pemb[(size_t)p1[st] * 5 + (c - 50)];
    else             v = pemb[(size_t)p2[st] * 5 + (c - 55)];
    g_x[idx] = v;
}

// ---------------- xp = x @ W_ih^T + b_ih  (both directions) ----------------
// grid: (179200/128=1400, 600/100=6, 2)  block: 320 (tx=tid%10, ty=tid/10)
// tile: 128 rows x 100 cols, K=60 (3 chunks of 20). FFMA2 packed over cols.
__global__ void __launch_bounds__(320, 2) xp_gemm_kernel(
    const float* __restrict__ Wf, const float* __restrict__ Wb,
    const float* __restrict__ bf, const float* __restrict__ bb)
{
    const int dir = blockIdx.z;
    const float* W    = dir ? Wb : Wf;
    const float* bias = dir ? bb : bf;
    float* xp = dir ? g_xp_b : g_xp_f;

    const int m0 = blockIdx.x * 128;
    const int c0 = blockIdx.y * 100;

    __shared__ unsigned long long As2[20][128];  // duplicated (a,a) pairs
    __shared__ float Bs[20][104];

    const int tid = threadIdx.x;
    const int tx = tid % 10;   // 10 cols (5 pairs) each
    const int ty = tid / 10;   // 32 -> 4 rows each

    unsigned long long acc[4][5];
    #pragma unroll
    for (int r = 0; r < 4; r++)
        #pragma unroll
        for (int p = 0; p < 5; p++) acc[r][p] = 0ULL;

    for (int k0 = 0; k0 < IND; k0 += 20) {
        // A fill: 128 rows x 20 k = 640 float4 tasks
        #pragma unroll
        for (int l = 0; l < 2; l++) {
            int task = tid + 320 * l;
            int row = task / 5, f4 = task % 5;
            float4 a4 = *(const float4*)&g_x[(size_t)(m0 + row) * IND + k0 + 4 * f4];
            As2[4 * f4 + 0][row] = pack2(a4.x, a4.x);
            As2[4 * f4 + 1][row] = pack2(a4.y, a4.y);
            As2[4 * f4 + 2][row] = pack2(a4.z, a4.z);
            As2[4 * f4 + 3][row] = pack2(a4.w, a4.w);
        }
        // B fill: 100 cols x 20 k = 2000 floats
        #pragma unroll
        for (int l = 0; l < 7; l++) {
            int e = tid + 320 * l;
            if (e < 2000) {
                int col = e / 20, kk = e % 20;
                Bs[kk][col] = W[(size_t)(c0 + col) * IND + k0 + kk];
            }
        }
        __syncthreads();
        #pragma unroll
        for (int k = 0; k < 20; k++) {
            unsigned long long bv[5];
            #pragma unroll
            for (int p = 0; p < 5; p++)
                bv[p] = *(const unsigned long long*)&Bs[k][10 * tx + 2 * p];
            #pragma unroll
            for (int r = 0; r < 4; r++) {
                unsigned long long a = As2[k][4 * ty + r];
                #pragma unroll
                for (int p = 0; p < 5; p++) ffma2(acc[r][p], a, bv[p]);
            }
        }
        __syncthreads();
    }

    #pragma unroll
    for (int r = 0; r < 4; r++) {
        int m = m0 + 4 * ty + r;
        int s = m / T_LEN, t = m - s * T_LEN;
        size_t base = ((size_t)t * S_TOT + s) * G3 + c0 + 10 * tx;
        #pragma unroll
        for (int p = 0; p < 5; p++) {
            float lo, hi;
            unpack2(acc[r][p], lo, hi);
            int c = c0 + 10 * tx + 2 * p;
            float2 v = make_float2(lo + bias[c], hi + bias[c + 1]);
            *(float2*)&xp[base + 2 * p] = v;
        }
    }
}

// ---------------- fused GRU step: gates GEMM + pointwise --------------------
// grid: (2560/128=20, ceil(200/32)=7, 2)  block: 256
// tile: 128 rows x 32 hidden (x3 gates), K=200 in 13 chunks of 16. FFMA2.
__global__ void __launch_bounds__(256, 2) gru_step_kernel(int step,
    const float* __restrict__ Whh_f, const float* __restrict__ Whh_b,
    const float* __restrict__ bhh_f, const float* __restrict__ bhh_b)
{
    const int dir = blockIdx.z;
    const int t = dir ? (T_LEN - 1 - step) : step;
    const float* W    = dir ? Whh_b : Whh_f;
    const float* bhh  = dir ? bhh_b : bhh_f;
    const float* hprev = g_h[dir][step & 1];
    float* hnext       = g_h[dir][(step + 1) & 1];
    const float* xp = (dir ? g_xp_b : g_xp_f) + (size_t)t * S_TOT * G3;
    float* seq      = (dir ? g_seq_b : g_seq_f) + (size_t)t * S_TOT * HIDN;

    const int row0 = blockIdx.x * 128;
    const int j0   = blockIdx.y * 32;

    __shared__ unsigned long long As2[16][128];   // duplicated (a,a)
    __shared__ float Bs[16][100];                 // [k][gate*32 + h]

    const int tid = threadIdx.x;
    const int tx = tid & 15;   // col pair: j0 + 2*tx
    const int ty = tid >> 4;   // 8 rows each

    unsigned long long acc[3][8];
    #pragma unroll
    for (int g = 0; g < 3; g++)
        #pragma unroll
        for (int r = 0; r < 8; r++) acc[g][r] = 0ULL;

    for (int k0 = 0; k0 < HIDN; k0 += 16) {
        // A fill: 128 rows x 16 k = 512 float4 tasks
        #pragma unroll
        for (int l = 0; l < 2; l++) {
            int task = tid + 256 * l;
            int row = task >> 2;
            int kg  = task & 3;
            float4 a4 = make_float4(0.f, 0.f, 0.f, 0.f);
            if (k0 + 4 * kg < HIDN)
                a4 = *(const float4*)&hprev[(size_t)(row0 + row) * HIDN + k0 + 4 * kg];
            As2[4 * kg + 0][row] = pack2(a4.x, a4.x);
            As2[4 * kg + 1][row] = pack2(a4.y, a4.y);
            As2[4 * kg + 2][row] = pack2(a4.z, a4.z);
            As2[4 * kg + 3][row] = pack2(a4.w, a4.w);
        }
        // B fill: 96 gate-rows x 16 k
        #pragma unroll
        for (int l = 0; l < 6; l++) {
            int e    = tid + 256 * l;
            int gl   = e >> 4;          // 0..95
            int kk   = e & 15;
            int gate = gl >> 5;
            int h    = gl & 31;
            float v = 0.f;
            if (j0 + h < HIDN && k0 + kk < HIDN)
                v = W[(size_t)(gate * HIDN + j0 + h) * HIDN + k0 + kk];
            Bs[kk][gl] = v;
        }
        __syncthreads();
        #pragma unroll
        for (int k = 0; k < 16; k++) {
            unsigned long long b0 = *(const unsigned long long*)&Bs[k][      2 * tx];
            unsigned long long b1 = *(const unsigned long long*)&Bs[k][32 +  2 * tx];
            unsigned long long b2 = *(const unsigned long long*)&Bs[k][64 +  2 * tx];
            #pragma unroll
            for (int r = 0; r < 8; r++) {
                unsigned long long a = As2[k][8 * ty + r];
                ffma2(acc[0][r], a, b0);
                ffma2(acc[1][r], a, b1);
                ffma2(acc[2][r], a, b2);
            }
        }
        __syncthreads();
    }

    const int j = j0 + 2 * tx;
    if (j < HIDN) {
        const float br0 = bhh[j],            br1 = bhh[j + 1];
        const float bz0 = bhh[HIDN + j],     bz1 = bhh[HIDN + j + 1];
        const float bn0 = bhh[2 * HIDN + j], bn1 = bhh[2 * HIDN + j + 1];
        #pragma unroll
        for (int r = 0; r < 8; r++) {
            int row = row0 + 8 * ty + r;
            const float* xr = xp + (size_t)row * G3;
            float2 xrv = *(const float2*)&xr[j];
            float2 xzv = *(const float2*)&xr[HIDN + j];
            float2 xnv = *(const float2*)&xr[2 * HIDN + j];
            float2 hpv = *(const float2*)&hprev[(size_t)row * HIDN + j];
            float gr0, gr1, gz0, gz1, gn0, gn1;
            unpack2(acc[0][r], gr0, gr1);
            unpack2(acc[1][r], gz0, gz1);
            unpack2(acc[2][r], gn0, gn1);

            float r0 = sigm(xrv.x + gr0 + br0);
            float z0 = sigm(xzv.x + gz0 + bz0);
            float n0 = tanhf(xnv.x + r0 * (gn0 + bn0));
            float h0 = (1.f - z0) * n0 + z0 * hpv.x;

            float r1 = sigm(xrv.y + gr1 + br1);
            float z1 = sigm(xzv.y + gz1 + bz1);
            float n1 = tanhf(xnv.y + r1 * (gn1 + bn1));
            float h1 = (1.f - z1) * n1 + z1 * hpv.y;

            float2 hv = make_float2(h0, h1);
            *(float2*)&hnext[(size_t)row * HIDN + j] = hv;
            *(float2*)&seq[(size_t)row * HIDN + j]   = hv;
        }
    }
}

// ---------------- word-level attention (tup cached in smem) -----------------
__global__ void __launch_bounds__(256) word_attn_kernel(const float* __restrict__ aw)
{
    extern __shared__ float tup[];       // [70][200]
    __shared__ float sc[T_LEN];
    const int s = blockIdx.x;
    const int lane = threadIdx.x & 31, wid = threadIdx.x >> 5;

    for (int t = wid; t < T_LEN; t += 8) {
        const float* f = g_seq_f + ((size_t)t * S_TOT + s) * HIDN;
        const float* b = g_seq_b + ((size_t)t * S_TOT + s) * HIDN;
        float sum = 0.f;
        for (int d = lane; d < HIDN; d += 32) {
            float v = f[d] + b[d];
            tup[t * HIDN + d] = v;
            sum += tanhf(v) * aw[d];
        }
        #pragma unroll
        for (int o = 16; o > 0; o >>= 1) sum += __shfl_xor_sync(0xffffffffu, sum, o);
        if (lane == 0) sc[t] = sum;
    }
    __syncthreads();
    if (threadIdx.x == 0) {
        float m = sc[0];
        for (int t = 1; t < T_LEN; t++) m = fmaxf(m, sc[t]);
        float ssum = 0.f;
        for (int t = 0; t < T_LEN; t++) { float e2 = expf(sc[t] - m); sc[t] = e2; ssum += e2; }
        float inv = 1.f / ssum;
        for (int t = 0; t < T_LEN; t++) sc[t] *= inv;
    }
    __syncthreads();
    for (int d = threadIdx.x; d < HIDN; d += 256) {
        float acc = 0.f;
        #pragma unroll 7
        for (int t = 0; t < T_LEN; t++) acc += sc[t] * tup[t * HIDN + d];
        g_H[(size_t)s * HIDN + d] = acc;
    }
}

// ---------------- bag attention + logits + BCE ------------------------------
__global__ void __launch_bounds__(128) bag_kernel(
    const float* __restrict__ sen_a, const float* __restrict__ sen_r,
    const float* __restrict__ rel, const float* __restrict__ sen_d,
    const int* __restrict__ label, float* __restrict__ logits)
{
    const int b = blockIdx.x;
    __shared__ float Hs[NSEN][HIDN];
    __shared__ float ew[NSEN];
    __shared__ float Sv[HIDN];
    __shared__ float red[128];

    for (int e = threadIdx.x; e < NSEN * HIDN; e += 128)
        Hs[e / HIDN][e % HIDN] = g_H[(size_t)b * NSEN * HIDN + e];
    __syncthreads();

    const int lane = threadIdx.x & 31, wid = threadIdx.x >> 5;
    for (int n = wid; n < NSEN; n += 4) {
        float sum = 0.f;
        for (int d = lane; d < HIDN; d += 32)
            sum += Hs[n][d] * sen_a[d] * sen_r[d];
        #pragma unroll
        for (int o = 16; o > 0; o >>= 1) sum += __shfl_xor_sync(0xffffffffu, sum, o);
        if (lane == 0) ew[n] = sum;
    }
    __syncthreads();
    if (threadIdx.x == 0) {
        float m = ew[0];
        for (int n = 1; n < NSEN; n++) m = fmaxf(m, ew[n]);
        float s2 = 0.f;
        for (int n = 0; n < NSEN; n++) { float e2 = expf(ew[n] - m); ew[n] = e2; s2 += e2; }
        float inv = 1.f / s2;
        for (int n = 0; n < NSEN; n++) ew[n] *= inv;
    }
    __syncthreads();
    for (int d = threadIdx.x; d < HIDN; d += 128) {
        float acc = 0.f;
        for (int n = 0; n < NSEN; n++) acc += ew[n] * Hs[n][d];
        Sv[d] = acc;
    }
    __syncthreads();

    int lab = label[b];
    float bce = 0.f;
    if (threadIdx.x < NREL) {
        int r = threadIdx.x;
        float l = sen_d[r];
        for (int d = 0; d < HIDN; d++) l += Sv[d] * rel[(size_t)r * HIDN + d];
        logits[(size_t)b * NREL + r] = l;
        float tgt = (lab == r) ? 1.f : 0.f;
        bce = fmaxf(l, 0.f) - l * tgt + log1pf(expf(-fabsf(l)));
    }
    red[threadIdx.x] = bce;
    __syncthreads();
    for (int o = 64; o > 0; o >>= 1) {
        if (threadIdx.x < o) red[threadIdx.x] += red[threadIdx.x + o];
        __syncthreads();
    }
    if (threadIdx.x == 0) g_bagloss[b] = red[0] / (float)NREL;
}

__global__ void loss_sum_kernel(float* __restrict__ out) {
    __shared__ float red[128];
    red[threadIdx.x] = g_bagloss[threadIdx.x];
    __syncthreads();
    for (int o = 64; o > 0; o >>= 1) {
        if (threadIdx.x < o) red[threadIdx.x] += red[threadIdx.x + o];
        __syncthreads();
    }
    if (threadIdx.x == 0) out[0] = red[0];
}

// ---------------- launch ----------------------------------------------------
extern "C" void kernel_launch(void* const* d_in, const int* in_sizes, int n_in,
                              void* d_out, int out_size)
{
    const int*   tok    = (const int*)d_in[0];
    const int*   p1     = (const int*)d_in[1];
    const int*   p2     = (const int*)d_in[2];
    const int*   lab    = (const int*)d_in[3];
    const float* emb    = (const float*)d_in[4];
    const float* pemb   = (const float*)d_in[5];
    const float* Wih_f  = (const float*)d_in[6];
    const float* Whh_f  = (const float*)d_in[7];
    const float* bih_f  = (const float*)d_in[8];
    const float* bhh_f  = (const float*)d_in[9];
    const float* Wih_b  = (const float*)d_in[10];
    const float* Whh_b  = (const float*)d_in[11];
    const float* bih_b  = (const float*)d_in[12];
    const float* bhh_b  = (const float*)d_in[13];
    const float* aw     = (const float*)d_in[14];
    const float* sen_a  = (const float*)d_in[15];
    const float* sen_r  = (const float*)d_in[16];
    const float* rel    = (const float*)d_in[17];
    const float* sen_d  = (const float*)d_in[18];
    float* out = (float*)d_out;

    init_h_kernel<<<(S_TOT * HIDN + 255) / 256, 256>>>();
    gather_kernel<<<(S_TOT * T_LEN * IND + 255) / 256, 256>>>(tok, p1, p2, emb, pemb);

    dim3 g2(S_TOT * T_LEN / 128, G3 / 100, 2);
    xp_gemm_kernel<<<g2, 320>>>(Wih_f, Wih_b, bih_f, bih_b);

    dim3 g3(S_TOT / 128, (HIDN + 31) / 32, 2);
    for (int step = 0; step < T_LEN; step++)
        gru_step_kernel<<<g3, 256>>>(step, Whh_f, Whh_b, bhh_f, bhh_b);

    static const int attn_smem = T_LEN * HIDN * (int)sizeof(float);  // 56000
    cudaFuncSetAttribute(word_attn_kernel,
                         cudaFuncAttributeMaxDynamicSharedMemorySize, attn_smem);
    word_attn_kernel<<<S_TOT, 256, attn_smem>>>(aw);
    bag_kernel<<<NBAG, 128>>>(sen_a, sen_r, rel, sen_d, lab, out + 1);
    loss_sum_kernel<<<1, 128>>>(out);
}

// round 5
// speedup vs baseline: 1.2485x; 1.1157x over previous
#include <cuda_runtime.h>
#include <math.h>

#define S_TOT 2560      // B*N sequences
#define T_LEN 70
#define HIDN  200
#define G3    600
#define IND   60
#define NBAG  128
#define NSEN  20
#define NREL  100

typedef unsigned long long ULL;

// ---------------- scratch (static device memory) ----------------------------
__device__ float g_x[S_TOT * T_LEN * IND];
__device__ float g_xp_f[(size_t)T_LEN * S_TOT * G3];
__device__ float g_xp_b[(size_t)T_LEN * S_TOT * G3];
__device__ float g_seq_f[(size_t)T_LEN * S_TOT * HIDN];
__device__ float g_seq_b[(size_t)T_LEN * S_TOT * HIDN];
__device__ float g_zero[S_TOT * HIDN];          // h0 = 0
__device__ float g_H[S_TOT * HIDN];
__device__ float g_bagloss[NBAG];
__device__ int   g_ctr[2][20];                  // per (dir,row-tile) step counters

__device__ __forceinline__ float sigm(float x) { return 1.f / (1.f + expf(-x)); }

__device__ __forceinline__ ULL pack2(float x, float y) {
    ULL r; asm("mov.b64 %0, {%1, %2};" : "=l"(r) : "f"(x), "f"(y)); return r;
}
__device__ __forceinline__ void ffma2(ULL& d, ULL a, ULL b) {
    asm("fma.rn.f32x2 %0, %1, %2, %0;" : "+l"(d) : "l"(a), "l"(b));
}
__device__ __forceinline__ void unpack2(ULL v, float& x, float& y) {
    asm("mov.b64 {%0, %1}, %2;" : "=f"(x), "=f"(y) : "l"(v));
}

// ---------------- init: zero h0 buffer + counters ----------------------------
__global__ void init_kernel() {
    int i = blockIdx.x * blockDim.x + threadIdx.x;
    if (i < S_TOT * HIDN) g_zero[i] = 0.f;
    if (i < 40) ((int*)g_ctr)[i] = 0;
}

// ---------------- embedding gather + concat ---------------------------------
__global__ void gather_kernel(const int* __restrict__ tok, const int* __restrict__ p1,
                              const int* __restrict__ p2, const float* __restrict__ emb,
                              const float* __restrict__ pemb) {
    int idx = blockIdx.x * blockDim.x + threadIdx.x;
    if (idx >= S_TOT * T_LEN * IND) return;
    int st = idx / IND;
    int c  = idx - st * IND;
    float v;
    if (c < 50)      v = emb[(size_t)tok[st] * 50 + c];
    else if (c < 55) v = pemb[(size_t)p1[st] * 5 + (c - 50)];
    else             v = pemb[(size_t)p2[st] * 5 + (c - 55)];
    g_x[idx] = v;
}

// ---------------- xp = x @ W_ih^T + b_ih  (both directions) -----------------
__global__ void __launch_bounds__(320, 2) xp_gemm_kernel(
    const float* __restrict__ Wf, const float* __restrict__ Wb,
    const float* __restrict__ bf, const float* __restrict__ bb)
{
    const int dir = blockIdx.z;
    const float* W    = dir ? Wb : Wf;
    const float* bias = dir ? bb : bf;
    float* xp = dir ? g_xp_b : g_xp_f;

    const int m0 = blockIdx.x * 128;
    const int c0 = blockIdx.y * 100;

    __shared__ ULL   As2[20][128];
    __shared__ float Bs[20][104];

    const int tid = threadIdx.x;
    const int tx = tid % 10;
    const int ty = tid / 10;

    ULL acc[4][5];
    #pragma unroll
    for (int r = 0; r < 4; r++)
        #pragma unroll
        for (int p = 0; p < 5; p++) acc[r][p] = 0ULL;

    for (int k0 = 0; k0 < IND; k0 += 20) {
        #pragma unroll
        for (int l = 0; l < 2; l++) {
            int task = tid + 320 * l;
            int row = task / 5, f4 = task % 5;
            float4 a4 = *(const float4*)&g_x[(size_t)(m0 + row) * IND + k0 + 4 * f4];
            As2[4 * f4 + 0][row] = pack2(a4.x, a4.x);
            As2[4 * f4 + 1][row] = pack2(a4.y, a4.y);
            As2[4 * f4 + 2][row] = pack2(a4.z, a4.z);
            As2[4 * f4 + 3][row] = pack2(a4.w, a4.w);
        }
        #pragma unroll
        for (int l = 0; l < 7; l++) {
            int e = tid + 320 * l;
            if (e < 2000) {
                int col = e / 20, kk = e % 20;
                Bs[kk][col] = W[(size_t)(c0 + col) * IND + k0 + kk];
            }
        }
        __syncthreads();
        #pragma unroll
        for (int k = 0; k < 20; k++) {
            ULL bv[5];
            #pragma unroll
            for (int p = 0; p < 5; p++)
                bv[p] = *(const ULL*)&Bs[k][10 * tx + 2 * p];
            #pragma unroll
            for (int r = 0; r < 4; r++) {
                ULL a = As2[k][4 * ty + r];
                #pragma unroll
                for (int p = 0; p < 5; p++) ffma2(acc[r][p], a, bv[p]);
            }
        }
        __syncthreads();
    }

    #pragma unroll
    for (int r = 0; r < 4; r++) {
        int m = m0 + 4 * ty + r;
        int s = m / T_LEN, t = m - s * T_LEN;
        size_t base = ((size_t)t * S_TOT + s) * G3 + c0 + 10 * tx;
        #pragma unroll
        for (int p = 0; p < 5; p++) {
            float lo, hi;
            unpack2(acc[r][p], lo, hi);
            int c = c0 + 10 * tx + 2 * p;
            float2 v = make_float2(lo + bias[c], hi + bias[c + 1]);
            *(float2*)&xp[base + 2 * p] = v;
        }
    }
}

// ---------------- persistent bidirectional GRU ------------------------------
// grid: dim3(7, 20, 2) = 280 blocks, 256 threads, 2 blocks/SM -> one wave.
// W slice cached in smem for the whole kernel. hprev = seq[t_prev].
// Inter-step sync: per (dir,row-tile) atomic counter among 7 blocks.
#define KCH 16
#define NCHUNK 13           // 13*16 = 208 >= 200 (padded with zeros)

__global__ void __launch_bounds__(256, 2) gru_persistent_kernel(
    const float* __restrict__ Whh_f, const float* __restrict__ Whh_b,
    const float* __restrict__ bhh_f, const float* __restrict__ bhh_b)
{
    extern __shared__ char smraw[];
    float* Bs = (float*)smraw;                         // [208][96] all k resident
    ULL*   As2 = (ULL*)(smraw + 208 * 96 * 4);         // [2][16][128]

    const int jb   = blockIdx.x;        // 0..6
    const int rowt = blockIdx.y;        // 0..19
    const int dir  = blockIdx.z;        // 0..1
    const int tid  = threadIdx.x;
    const int tx   = tid & 7;           // 8 col-groups of 4
    const int ty   = tid >> 3;          // 32 row-groups of 4

    const int row0 = rowt * 128;
    const int j0   = jb * 32;
    const int j    = j0 + 4 * tx;
    const bool jvalid = (j < HIDN);

    const float* W    = dir ? Whh_b : Whh_f;
    const float* bhh  = dir ? bhh_b : bhh_f;
    const float* xpb  = dir ? g_xp_b : g_xp_f;
    float*       seqb = dir ? g_seq_b : g_seq_f;

    // ---- load W slice into smem once (coalesced over k) ----
    for (int e = tid; e < 96 * 208; e += 256) {
        int c = e / 208;          // 0..95
        int k = e % 208;          // 0..207
        int g = c >> 5, h = c & 31;
        int col = j0 + h;
        float v = 0.f;
        if (k < HIDN && col < HIDN)
            v = W[((size_t)g * HIDN + col) * HIDN + k];
        Bs[k * 96 + c] = v;
    }

    // ---- bias registers ----
    float br[4] = {0,0,0,0}, bz[4] = {0,0,0,0}, bn[4] = {0,0,0,0};
    if (jvalid) {
        #pragma unroll
        for (int cc = 0; cc < 4; cc++) {
            br[cc] = bhh[j + cc];
            bz[cc] = bhh[HIDN + j + cc];
            bn[cc] = bhh[2 * HIDN + j + cc];
        }
    }
    __syncthreads();

    int* ctr = &g_ctr[dir][rowt];

    for (int s = 0; s < T_LEN; s++) {
        const int t = dir ? (T_LEN - 1 - s) : s;
        const int tprev = dir ? (t + 1) : (t - 1);
        const float* hprev = (s == 0) ? g_zero
                                      : seqb + (size_t)tprev * S_TOT * HIDN;
        const float* xp_t  = xpb + (size_t)t * S_TOT * G3;
        float*       seq_t = seqb + (size_t)t * S_TOT * HIDN;

        // prefetch this step's xp slice to L2
        #pragma unroll
        for (int l = 0; l < 3; l++) {
            int idx = tid + 256 * l;
            if (idx < 768) {
                int row = idx / 6, rem = idx % 6;
                int g = rem >> 1, half = rem & 1;
                const float* p = xp_t + (size_t)(row0 + row) * G3 + g * HIDN + j0 + half * 32;
                asm volatile("prefetch.global.L2 [%0];" :: "l"(p));
            }
        }

        ULL acc[3][4][2];
        #pragma unroll
        for (int g = 0; g < 3; g++)
            #pragma unroll
            for (int r = 0; r < 4; r++) { acc[g][r][0] = 0ULL; acc[g][r][1] = 0ULL; }

        if (s > 0) {
            // preload chunk 0
            #pragma unroll
            for (int l = 0; l < 2; l++) {
                int task = tid + 256 * l;
                int row = task >> 2, kg = task & 3;
                float4 a4 = *(const float4*)&hprev[(size_t)(row0 + row) * HIDN + 4 * kg];
                ULL* dst = As2 + (size_t)(4 * kg) * 128 + row;
                dst[0]   = pack2(a4.x, a4.x);
                dst[128] = pack2(a4.y, a4.y);
                dst[256] = pack2(a4.z, a4.z);
                dst[384] = pack2(a4.w, a4.w);
            }
            __syncthreads();

            for (int c = 0; c < NCHUNK; c++) {
                const int buf = c & 1;
                const bool more = (c + 1 < NCHUNK);
                float4 st0, st1;
                int row_a = (tid      ) >> 2, kg_a = (tid      ) & 3;
                int row_b = (tid + 256) >> 2, kg_b = (tid + 256) & 3;
                if (more) {
                    int k0n = (c + 1) * KCH;
                    st0 = make_float4(0.f, 0.f, 0.f, 0.f);
                    st1 = st0;
                    if (k0n + 4 * kg_a < HIDN)
                        st0 = *(const float4*)&hprev[(size_t)(row0 + row_a) * HIDN + k0n + 4 * kg_a];
                    if (k0n + 4 * kg_b < HIDN)
                        st1 = *(const float4*)&hprev[(size_t)(row0 + row_b) * HIDN + k0n + 4 * kg_b];
                }

                const ULL* Ab = As2 + (size_t)buf * (KCH * 128);
                #pragma unroll
                for (int k = 0; k < KCH; k++) {
                    const ULL*   ak = Ab + k * 128 + 4 * ty;
                    // FIXED: weight k-index must be global (c*KCH + k), Bs holds all 208 rows
                    const float* bk = Bs + (size_t)(c * KCH + k) * 96 + 4 * tx;
                    ulonglong2 a01 = *(const ulonglong2*)(ak);
                    ulonglong2 a23 = *(const ulonglong2*)(ak + 2);
                    ulonglong2 b0 = *(const ulonglong2*)(bk);
                    ulonglong2 b1 = *(const ulonglong2*)(bk + 32);
                    ulonglong2 b2 = *(const ulonglong2*)(bk + 64);
                    ULL av[4] = {a01.x, a01.y, a23.x, a23.y};
                    #pragma unroll
                    for (int r = 0; r < 4; r++) {
                        ffma2(acc[0][r][0], av[r], b0.x);
                        ffma2(acc[0][r][1], av[r], b0.y);
                        ffma2(acc[1][r][0], av[r], b1.x);
                        ffma2(acc[1][r][1], av[r], b1.y);
                        ffma2(acc[2][r][0], av[r], b2.x);
                        ffma2(acc[2][r][1], av[r], b2.y);
                    }
                }
                __syncthreads();
                if (more) {
                    ULL* Anb = As2 + (size_t)(buf ^ 1) * (KCH * 128);
                    ULL* d0 = Anb + (size_t)(4 * kg_a) * 128 + row_a;
                    d0[0]   = pack2(st0.x, st0.x);
                    d0[128] = pack2(st0.y, st0.y);
                    d0[256] = pack2(st0.z, st0.z);
                    d0[384] = pack2(st0.w, st0.w);
                    ULL* d1 = Anb + (size_t)(4 * kg_b) * 128 + row_b;
                    d1[0]   = pack2(st1.x, st1.x);
                    d1[128] = pack2(st1.y, st1.y);
                    d1[256] = pack2(st1.z, st1.z);
                    d1[384] = pack2(st1.w, st1.w);
                    __syncthreads();
                }
            }
        }

        // ---- epilogue: gates -> h, write seq[t] ----
        if (jvalid) {
            #pragma unroll
            for (int r = 0; r < 4; r++) {
                int row = row0 + 4 * ty + r;
                const float* xr = xp_t + (size_t)row * G3;
                float4 xrv = *(const float4*)&xr[j];
                float4 xzv = *(const float4*)&xr[HIDN + j];
                float4 xnv = *(const float4*)&xr[2 * HIDN + j];
                float4 hpv = *(const float4*)&hprev[(size_t)row * HIDN + j];
                float gr[4], gz[4], gn[4];
                unpack2(acc[0][r][0], gr[0], gr[1]); unpack2(acc[0][r][1], gr[2], gr[3]);
                unpack2(acc[1][r][0], gz[0], gz[1]); unpack2(acc[1][r][1], gz[2], gz[3]);
                unpack2(acc[2][r][0], gn[0], gn[1]); unpack2(acc[2][r][1], gn[2], gn[3]);
                float xv[4] = {xrv.x, xrv.y, xrv.z, xrv.w};
                float zv[4] = {xzv.x, xzv.y, xzv.z, xzv.w};
                float nv[4] = {xnv.x, xnv.y, xnv.z, xnv.w};
                float hv[4] = {hpv.x, hpv.y, hpv.z, hpv.w};
                float out[4];
                #pragma unroll
                for (int cc = 0; cc < 4; cc++) {
                    float rr = sigm(xv[cc] + gr[cc] + br[cc]);
                    float zz = sigm(zv[cc] + gz[cc] + bz[cc]);
                    float nn = tanhf(nv[cc] + rr * (gn[cc] + bn[cc]));
                    out[cc] = (1.f - zz) * nn + zz * hv[cc];
                }
                *(float4*)&seq_t[(size_t)row * HIDN + j] =
                    make_float4(out[0], out[1], out[2], out[3]);
            }
        }

        // ---- group sync: 7 blocks sharing (dir,row-tile) ----
        __threadfence();
        __syncthreads();
        if (tid == 0) {
            atomicAdd(ctr, 1);
            int target = 7 * (s + 1);
            while (*(volatile int*)ctr < target) { }
            __threadfence();
        }
        __syncthreads();
    }
}

// ---------------- word-level attention (tup cached in smem) -----------------
__global__ void __launch_bounds__(256) word_attn_kernel(const float* __restrict__ aw)
{
    extern __shared__ float tup[];       // [70][200]
    __shared__ float sc[T_LEN];
    const int s = blockIdx.x;
    const int lane = threadIdx.x & 31, wid = threadIdx.x >> 5;

    for (int t = wid; t < T_LEN; t += 8) {
        const float* f = g_seq_f + ((size_t)t * S_TOT + s) * HIDN;
        const float* b = g_seq_b + ((size_t)t * S_TOT + s) * HIDN;
        float sum = 0.f;
        for (int d = lane; d < HIDN; d += 32) {
            float v = f[d] + b[d];
            tup[t * HIDN + d] = v;
            sum += tanhf(v) * aw[d];
        }
        #pragma unroll
        for (int o = 16; o > 0; o >>= 1) sum += __shfl_xor_sync(0xffffffffu, sum, o);
        if (lane == 0) sc[t] = sum;
    }
    __syncthreads();
    if (threadIdx.x == 0) {
        float m = sc[0];
        for (int t = 1; t < T_LEN; t++) m = fmaxf(m, sc[t]);
        float ssum = 0.f;
        for (int t = 0; t < T_LEN; t++) { float e2 = expf(sc[t] - m); sc[t] = e2; ssum += e2; }
        float inv = 1.f / ssum;
        for (int t = 0; t < T_LEN; t++) sc[t] *= inv;
    }
    __syncthreads();
    for (int d = threadIdx.x; d < HIDN; d += 256) {
        float acc = 0.f;
        #pragma unroll 7
        for (int t = 0; t < T_LEN; t++) acc += sc[t] * tup[t * HIDN + d];
        g_H[(size_t)s * HIDN + d] = acc;
    }
}

// ---------------- bag attention + logits + BCE ------------------------------
__global__ void __launch_bounds__(128) bag_kernel(
    const float* __restrict__ sen_a, const float* __restrict__ sen_r,
    const float* __restrict__ rel, const float* __restrict__ sen_d,
    const int* __restrict__ label, float* __restrict__ logits)
{
    const int b = blockIdx.x;
    __shared__ float Hs[NSEN][HIDN];
    __shared__ float ew[NSEN];
    __shared__ float Sv[HIDN];
    __shared__ float red[128];

    for (int e = threadIdx.x; e < NSEN * HIDN; e += 128)
        Hs[e / HIDN][e % HIDN] = g_H[(size_t)b * NSEN * HIDN + e];
    __syncthreads();

    const int lane = threadIdx.x & 31, wid = threadIdx.x >> 5;
    for (int n = wid; n < NSEN; n += 4) {
        float sum = 0.f;
        for (int d = lane; d < HIDN; d += 32)
            sum += Hs[n][d] * sen_a[d] * sen_r[d];
        #pragma unroll
        for (int o = 16; o > 0; o >>= 1) sum += __shfl_xor_sync(0xffffffffu, sum, o);
        if (lane == 0) ew[n] = sum;
    }
    __syncthreads();
    if (threadIdx.x == 0) {
        float m = ew[0];
        for (int n = 1; n < NSEN; n++) m = fmaxf(m, ew[n]);
        float s2 = 0.f;
        for (int n = 0; n < NSEN; n++) { float e2 = expf(ew[n] - m); ew[n] = e2; s2 += e2; }
        float inv = 1.f / s2;
        for (int n = 0; n < NSEN; n++) ew[n] *= inv;
    }
    __syncthreads();
    for (int d = threadIdx.x; d < HIDN; d += 128) {
        float acc = 0.f;
        for (int n = 0; n < NSEN; n++) acc += ew[n] * Hs[n][d];
        Sv[d] = acc;
    }
    __syncthreads();

    int lab = label[b];
    float bce = 0.f;
    if (threadIdx.x < NREL) {
        int r = threadIdx.x;
        float l = sen_d[r];
        for (int d = 0; d < HIDN; d++) l += Sv[d] * rel[(size_t)r * HIDN + d];
        logits[(size_t)b * NREL + r] = l;
        float tgt = (lab == r) ? 1.f : 0.f;
        bce = fmaxf(l, 0.f) - l * tgt + log1pf(expf(-fabsf(l)));
    }
    red[threadIdx.x] = bce;
    __syncthreads();
    for (int o = 64; o > 0; o >>= 1) {
        if (threadIdx.x < o) red[threadIdx.x] += red[threadIdx.x + o];
        __syncthreads();
    }
    if (threadIdx.x == 0) g_bagloss[b] = red[0] / (float)NREL;
}

__global__ void loss_sum_kernel(float* __restrict__ out) {
    __shared__ float red[128];
    red[threadIdx.x] = g_bagloss[threadIdx.x];
    __syncthreads();
    for (int o = 64; o > 0; o >>= 1) {
        if (threadIdx.x < o) red[threadIdx.x] += red[threadIdx.x + o];
        __syncthreads();
    }
    if (threadIdx.x == 0) out[0] = red[0];
}

// ---------------- launch ----------------------------------------------------
extern "C" void kernel_launch(void* const* d_in, const int* in_sizes, int n_in,
                              void* d_out, int out_size)
{
    const int*   tok    = (const int*)d_in[0];
    const int*   p1     = (const int*)d_in[1];
    const int*   p2     = (const int*)d_in[2];
    const int*   lab    = (const int*)d_in[3];
    const float* emb    = (const float*)d_in[4];
    const float* pemb   = (const float*)d_in[5];
    const float* Wih_f  = (const float*)d_in[6];
    const float* Whh_f  = (const float*)d_in[7];
    const float* bih_f  = (const float*)d_in[8];
    const float* bhh_f  = (const float*)d_in[9];
    const float* Wih_b  = (const float*)d_in[10];
    const float* Whh_b  = (const float*)d_in[11];
    const float* bih_b  = (const float*)d_in[12];
    const float* bhh_b  = (const float*)d_in[13];
    const float* aw     = (const float*)d_in[14];
    const float* sen_a  = (const float*)d_in[15];
    const float* sen_r  = (const float*)d_in[16];
    const float* rel    = (const float*)d_in[17];
    const float* sen_d  = (const float*)d_in[18];
    float* out = (float*)d_out;

    init_kernel<<<(S_TOT * HIDN + 255) / 256, 256>>>();
    gather_kernel<<<(S_TOT * T_LEN * IND + 255) / 256, 256>>>(tok, p1, p2, emb, pemb);

    dim3 g2(S_TOT * T_LEN / 128, G3 / 100, 2);
    xp_gemm_kernel<<<g2, 320>>>(Wih_f, Wih_b, bih_f, bih_b);

    static const int gru_smem = 208 * 96 * 4 + 2 * KCH * 128 * 8;   // 112640
    cudaFuncSetAttribute(gru_persistent_kernel,
                         cudaFuncAttributeMaxDynamicSharedMemorySize, gru_smem);
    dim3 g3(7, 20, 2);
    gru_persistent_kernel<<<g3, 256, gru_smem>>>(Whh_f, Whh_b, bhh_f, bhh_b);

    static const int attn_smem = T_LEN * HIDN * (int)sizeof(float);  // 56000
    cudaFuncSetAttribute(word_attn_kernel,
                         cudaFuncAttributeMaxDynamicSharedMemorySize, attn_smem);
    word_attn_kernel<<<S_TOT, 256, attn_smem>>>(aw);
    bag_kernel<<<NBAG, 128>>>(sen_a, sen_r, rel, sen_d, lab, out + 1);
    loss_sum_kernel<<<1, 128>>>(out);
}

// round 6
// speedup vs baseline: 1.4073x; 1.1271x over previous
#include <cuda_runtime.h>
#include <math.h>

#define S_TOT 2560      // B*N sequences
#define T_LEN 70
#define HIDN  200
#define G3    600
#define IND   60
#define NBAG  128
#define NSEN  20
#define NREL  100

typedef unsigned long long ULL;

// ---------------- scratch (static device memory) ----------------------------
__device__ float g_x[S_TOT * T_LEN * IND];
__device__ float g_xp_f[(size_t)T_LEN * S_TOT * G3];
__device__ float g_xp_b[(size_t)T_LEN * S_TOT * G3];
__device__ float g_seq_f[(size_t)T_LEN * S_TOT * HIDN];
__device__ float g_seq_b[(size_t)T_LEN * S_TOT * HIDN];
__device__ float g_zero[S_TOT * HIDN];          // h0 = 0
__device__ float g_H[S_TOT * HIDN];
__device__ float g_bagloss[NBAG];
__device__ int   g_ctr[2][20];                  // per (dir,row-tile) step counters

__device__ __forceinline__ float sigm(float x) { return 1.f / (1.f + expf(-x)); }

__device__ __forceinline__ ULL pack2(float x, float y) {
    ULL r; asm("mov.b64 %0, {%1, %2};" : "=l"(r) : "f"(x), "f"(y)); return r;
}
__device__ __forceinline__ void ffma2(ULL& d, ULL a, ULL b) {
    asm("fma.rn.f32x2 %0, %1, %2, %0;" : "+l"(d) : "l"(a), "l"(b));
}
__device__ __forceinline__ void unpack2(ULL v, float& x, float& y) {
    asm("mov.b64 {%0, %1}, %2;" : "=f"(x), "=f"(y) : "l"(v));
}

// ---------------- init: zero h0 buffer + counters ----------------------------
__global__ void init_kernel() {
    int i = blockIdx.x * blockDim.x + threadIdx.x;
    if (i < S_TOT * HIDN) g_zero[i] = 0.f;
    if (i < 40) ((int*)g_ctr)[i] = 0;
}

// ---------------- embedding gather + concat ---------------------------------
__global__ void gather_kernel(const int* __restrict__ tok, const int* __restrict__ p1,
                              const int* __restrict__ p2, const float* __restrict__ emb,
                              const float* __restrict__ pemb) {
    int idx = blockIdx.x * blockDim.x + threadIdx.x;
    if (idx >= S_TOT * T_LEN * IND) return;
    int st = idx / IND;
    int c  = idx - st * IND;
    float v;
    if (c < 50)      v = emb[(size_t)tok[st] * 50 + c];
    else if (c < 55) v = pemb[(size_t)p1[st] * 5 + (c - 50)];
    else             v = pemb[(size_t)p2[st] * 5 + (c - 55)];
    g_x[idx] = v;
}

// ---------------- xp = x @ W_ih^T + b_ih  (both directions) -----------------
// grid: (179200/256=700, 6, 2)  block: 320
// tile: 256 rows x 100 cols, K=60 (3 chunks of 20). 8 rows x 10 cols / thread.
// A staged natural (no duplication), pairs built in registers.
__global__ void __launch_bounds__(320) xp_gemm_kernel(
    const float* __restrict__ Wf, const float* __restrict__ Wb,
    const float* __restrict__ bf, const float* __restrict__ bb)
{
    const int dir = blockIdx.z;
    const float* W    = dir ? Wb : Wf;
    const float* bias = dir ? bb : bf;
    float* xp = dir ? g_xp_b : g_xp_f;

    const int m0 = blockIdx.x * 256;
    const int c0 = blockIdx.y * 100;

    __shared__ float As[2][20][256];
    __shared__ float Bs[2][20][104];

    const int tid = threadIdx.x;
    const int tx = tid % 10;       // 10 cols
    const int ty = tid / 10;       // 0..31 -> 8 rows each

    ULL acc[8][5];
    #pragma unroll
    for (int r = 0; r < 8; r++)
        #pragma unroll
        for (int p = 0; p < 5; p++) acc[r][p] = 0ULL;

    // ---- stage chunk 0 ----
    #pragma unroll
    for (int i = 0; i < 4; i++) {
        int task = tid + 320 * i;               // 0..1279
        int row = task & 255, kq = task >> 8;   // kq 0..4
        float4 v = *(const float4*)&g_x[(size_t)(m0 + row) * IND + 4 * kq];
        As[0][4 * kq + 0][row] = v.x;
        As[0][4 * kq + 1][row] = v.y;
        As[0][4 * kq + 2][row] = v.z;
        As[0][4 * kq + 3][row] = v.w;
    }
    #pragma unroll
    for (int i = 0; i < 2; i++) {
        int task = tid + 320 * i;               // need < 500
        if (task < 500) {
            int col = task % 100, kq = task / 100;
            float4 v = *(const float4*)&W[(size_t)(c0 + col) * IND + 4 * kq];
            Bs[0][4 * kq + 0][col] = v.x;
            Bs[0][4 * kq + 1][col] = v.y;
            Bs[0][4 * kq + 2][col] = v.z;
            Bs[0][4 * kq + 3][col] = v.w;
        }
    }
    __syncthreads();

    for (int c = 0; c < 3; c++) {
        const int buf = c & 1;
        const bool more = (c < 2);
        float4 sta[4], stb[2];
        if (more) {
            int k0n = (c + 1) * 20;
            #pragma unroll
            for (int i = 0; i < 4; i++) {
                int task = tid + 320 * i;
                int row = task & 255, kq = task >> 8;
                sta[i] = *(const float4*)&g_x[(size_t)(m0 + row) * IND + k0n + 4 * kq];
            }
            #pragma unroll
            for (int i = 0; i < 2; i++) {
                int task = tid + 320 * i;
                if (task < 500) {
                    int col = task % 100, kq = task / 100;
                    stb[i] = *(const float4*)&W[(size_t)(c0 + col) * IND + k0n + 4 * kq];
                }
            }
        }
        #pragma unroll 5
        for (int k = 0; k < 20; k++) {
            float4 a0 = *(const float4*)&As[buf][k][8 * ty];
            float4 a1 = *(const float4*)&As[buf][k][8 * ty + 4];
            ULL ap[8];
            ap[0] = pack2(a0.x, a0.x); ap[1] = pack2(a0.y, a0.y);
            ap[2] = pack2(a0.z, a0.z); ap[3] = pack2(a0.w, a0.w);
            ap[4] = pack2(a1.x, a1.x); ap[5] = pack2(a1.y, a1.y);
            ap[6] = pack2(a1.z, a1.z); ap[7] = pack2(a1.w, a1.w);
            ULL bv[5];
            #pragma unroll
            for (int p = 0; p < 5; p++)
                bv[p] = *(const ULL*)&Bs[buf][k][10 * tx + 2 * p];
            #pragma unroll
            for (int r = 0; r < 8; r++)
                #pragma unroll
                for (int p = 0; p < 5; p++) ffma2(acc[r][p], ap[r], bv[p]);
        }
        __syncthreads();
        if (more) {
            #pragma unroll
            for (int i = 0; i < 4; i++) {
                int task = tid + 320 * i;
                int row = task & 255, kq = task >> 8;
                As[buf ^ 1][4 * kq + 0][row] = sta[i].x;
                As[buf ^ 1][4 * kq + 1][row] = sta[i].y;
                As[buf ^ 1][4 * kq + 2][row] = sta[i].z;
                As[buf ^ 1][4 * kq + 3][row] = sta[i].w;
            }
            #pragma unroll
            for (int i = 0; i < 2; i++) {
                int task = tid + 320 * i;
                if (task < 500) {
                    int col = task % 100, kq = task / 100;
                    Bs[buf ^ 1][4 * kq + 0][col] = stb[i].x;
                    Bs[buf ^ 1][4 * kq + 1][col] = stb[i].y;
                    Bs[buf ^ 1][4 * kq + 2][col] = stb[i].z;
                    Bs[buf ^ 1][4 * kq + 3][col] = stb[i].w;
                }
            }
            __syncthreads();
        }
    }

    #pragma unroll
    for (int r = 0; r < 8; r++) {
        int m = m0 + 8 * ty + r;
        int s = m / T_LEN, t = m - s * T_LEN;
        size_t base = ((size_t)t * S_TOT + s) * G3 + c0 + 10 * tx;
        #pragma unroll
        for (int p = 0; p < 5; p++) {
            float lo, hi;
            unpack2(acc[r][p], lo, hi);
            int cc = c0 + 10 * tx + 2 * p;
            *(float2*)&xp[base + 2 * p] = make_float2(lo + bias[cc], hi + bias[cc + 1]);
        }
    }
}

// ---------------- persistent bidirectional GRU ------------------------------
// grid (7,20,2) = 280 CTAs, 128 threads, 2/SM -> one wave.
// Per thread: 8 rows x 4 cols x 3 gates. A staged natural, pairs in registers.
// W slice resident in smem. hprev = seq[t_prev]. Spin-sync among 7 CTAs.
#define KCH 20
#define NCHUNK 10           // 10*20 = 200 exact

__global__ void __launch_bounds__(128, 2) gru_persistent_kernel(
    const float* __restrict__ Whh_f, const float* __restrict__ Whh_b,
    const float* __restrict__ bhh_f, const float* __restrict__ bhh_b)
{
    extern __shared__ char smraw[];
    float* Ws = (float*)smraw;                     // [200][96]
    float* As = (float*)(smraw + 200 * 96 * 4);    // [2][20][128]

    const int jb   = blockIdx.x;        // 0..6
    const int rowt = blockIdx.y;        // 0..19
    const int dir  = blockIdx.z;
    const int tid  = threadIdx.x;
    const int tx   = tid & 7;           // col group: 4 cols
    const int ty   = tid >> 3;          // 0..15 -> 8 rows each
    const int row0 = rowt * 128;
    const int j0   = jb * 32;
    const int j    = j0 + 4 * tx;
    const bool jv  = (j < HIDN);

    const float* W    = dir ? Whh_b : Whh_f;
    const float* bhh  = dir ? bhh_b : bhh_f;
    const float* xpb  = dir ? g_xp_b : g_xp_f;
    float*       seqb = dir ? g_seq_b : g_seq_f;

    // ---- W slice to smem once ----
    for (int e = tid; e < 96 * HIDN; e += 128) {
        int c = e / HIDN;
        int k = e - c * HIDN;
        int g = c >> 5, h = c & 31;
        int col = j0 + h;
        Ws[k * 96 + c] = (col < HIDN)
            ? W[((size_t)g * HIDN + col) * HIDN + k] : 0.f;
    }

    float br[4] = {0,0,0,0}, bz[4] = {0,0,0,0}, bn[4] = {0,0,0,0};
    if (jv) {
        #pragma unroll
        for (int cc = 0; cc < 4; cc++) {
            br[cc] = bhh[j + cc];
            bz[cc] = bhh[HIDN + j + cc];
            bn[cc] = bhh[2 * HIDN + j + cc];
        }
    }
    __syncthreads();

    int* ctr = &g_ctr[dir][rowt];
    const int myrow = row0 + tid;       // staging: one row per thread

    for (int s = 0; s < T_LEN; s++) {
        const int t = dir ? (T_LEN - 1 - s) : s;
        const int tprev = dir ? (t + 1) : (t - 1);
        const float* hprev = (s == 0) ? g_zero
                                      : seqb + (size_t)tprev * S_TOT * HIDN;
        const float* xp_t  = xpb + (size_t)t * S_TOT * G3;
        float*       seq_t = seqb + (size_t)t * S_TOT * HIDN;

        // prefetch this step's xp working set to L2 (row = tid covers tile)
        {
            const float* pf = xp_t + (size_t)myrow * G3 + j0;
            #pragma unroll
            for (int g = 0; g < 3; g++) {
                asm volatile("prefetch.global.L2 [%0];" :: "l"(pf + g * HIDN));
                asm volatile("prefetch.global.L2 [%0];" :: "l"(pf + g * HIDN + 31));
            }
        }

        ULL acc[3][8][2];
        #pragma unroll
        for (int g = 0; g < 3; g++)
            #pragma unroll
            for (int r = 0; r < 8; r++) { acc[g][r][0] = 0ULL; acc[g][r][1] = 0ULL; }

        if (s > 0) {
            // preload chunk 0 (natural layout, one row per thread)
            #pragma unroll
            for (int i = 0; i < 5; i++) {
                float4 v = *(const float4*)&hprev[(size_t)myrow * HIDN + 4 * i];
                As[(4 * i + 0) * 128 + tid] = v.x;
                As[(4 * i + 1) * 128 + tid] = v.y;
                As[(4 * i + 2) * 128 + tid] = v.z;
                As[(4 * i + 3) * 128 + tid] = v.w;
            }
            __syncthreads();

            for (int c = 0; c < NCHUNK; c++) {
                const int buf = c & 1;
                const bool more = (c + 1 < NCHUNK);
                float4 st[5];
                if (more) {
                    int k0n = (c + 1) * KCH;
                    #pragma unroll
                    for (int i = 0; i < 5; i++)
                        st[i] = *(const float4*)&hprev[(size_t)myrow * HIDN + k0n + 4 * i];
                }

                const float* Ab = As + buf * (KCH * 128);
                #pragma unroll 5
                for (int k = 0; k < KCH; k++) {
                    float4 a0 = *(const float4*)&Ab[k * 128 + 8 * ty];
                    float4 a1 = *(const float4*)&Ab[k * 128 + 8 * ty + 4];
                    ULL ap[8];
                    ap[0] = pack2(a0.x, a0.x); ap[1] = pack2(a0.y, a0.y);
                    ap[2] = pack2(a0.z, a0.z); ap[3] = pack2(a0.w, a0.w);
                    ap[4] = pack2(a1.x, a1.x); ap[5] = pack2(a1.y, a1.y);
                    ap[6] = pack2(a1.z, a1.z); ap[7] = pack2(a1.w, a1.w);
                    const float* bk = Ws + (size_t)(c * KCH + k) * 96 + 4 * tx;
                    ulonglong2 b0 = *(const ulonglong2*)(bk);
                    ulonglong2 b1 = *(const ulonglong2*)(bk + 32);
                    ulonglong2 b2 = *(const ulonglong2*)(bk + 64);
                    #pragma unroll
                    for (int r = 0; r < 8; r++) {
                        ffma2(acc[0][r][0], ap[r], b0.x);
                        ffma2(acc[0][r][1], ap[r], b0.y);
                        ffma2(acc[1][r][0], ap[r], b1.x);
                        ffma2(acc[1][r][1], ap[r], b1.y);
                        ffma2(acc[2][r][0], ap[r], b2.x);
                        ffma2(acc[2][r][1], ap[r], b2.y);
                    }
                }
                __syncthreads();
                if (more) {
                    float* An = As + (buf ^ 1) * (KCH * 128);
                    #pragma unroll
                    for (int i = 0; i < 5; i++) {
                        An[(4 * i + 0) * 128 + tid] = st[i].x;
                        An[(4 * i + 1) * 128 + tid] = st[i].y;
                        An[(4 * i + 2) * 128 + tid] = st[i].z;
                        An[(4 * i + 3) * 128 + tid] = st[i].w;
                    }
                    __syncthreads();
                }
            }
        }

        // ---- epilogue: gates -> h, write seq[t] ----
        if (jv) {
            #pragma unroll
            for (int rr = 0; rr < 8; rr++) {
                int row = row0 + 8 * ty + rr;
                const float* xr = xp_t + (size_t)row * G3;
                float4 xrv = *(const float4*)&xr[j];
                float4 xzv = *(const float4*)&xr[HIDN + j];
                float4 xnv = *(const float4*)&xr[2 * HIDN + j];
                float4 hpv = *(const float4*)&hprev[(size_t)row * HIDN + j];
                float gr[4], gz[4], gn[4];
                unpack2(acc[0][rr][0], gr[0], gr[1]); unpack2(acc[0][rr][1], gr[2], gr[3]);
                unpack2(acc[1][rr][0], gz[0], gz[1]); unpack2(acc[1][rr][1], gz[2], gz[3]);
                unpack2(acc[2][rr][0], gn[0], gn[1]); unpack2(acc[2][rr][1], gn[2], gn[3]);
                float xv[4] = {xrv.x, xrv.y, xrv.z, xrv.w};
                float zv[4] = {xzv.x, xzv.y, xzv.z, xzv.w};
                float nv[4] = {xnv.x, xnv.y, xnv.z, xnv.w};
                float hv[4] = {hpv.x, hpv.y, hpv.z, hpv.w};
                float out[4];
                #pragma unroll
                for (int cc = 0; cc < 4; cc++) {
                    float rg = sigm(xv[cc] + gr[cc] + br[cc]);
                    float zg = sigm(zv[cc] + gz[cc] + bz[cc]);
                    float ng = tanhf(nv[cc] + rg * (gn[cc] + bn[cc]));
                    out[cc] = (1.f - zg) * ng + zg * hv[cc];
                }
                *(float4*)&seq_t[(size_t)row * HIDN + j] =
                    make_float4(out[0], out[1], out[2], out[3]);
            }
        }

        // ---- group sync: 7 CTAs sharing (dir,row-tile) ----
        __threadfence();
        __syncthreads();
        if (tid == 0) {
            atomicAdd(ctr, 1);
            int target = 7 * (s + 1);
            while (*(volatile int*)ctr < target) { }
            __threadfence();
        }
        __syncthreads();
    }
}

// ---------------- word-level attention (tup cached in smem) -----------------
__global__ void __launch_bounds__(256) word_attn_kernel(const float* __restrict__ aw)
{
    extern __shared__ float tup[];       // [70][200]
    __shared__ float sc[T_LEN];
    const int s = blockIdx.x;
    const int lane = threadIdx.x & 31, wid = threadIdx.x >> 5;

    for (int t = wid; t < T_LEN; t += 8) {
        const float* f = g_seq_f + ((size_t)t * S_TOT + s) * HIDN;
        const float* b = g_seq_b + ((size_t)t * S_TOT + s) * HIDN;
        float sum = 0.f;
        for (int d = lane; d < HIDN; d += 32) {
            float v = f[d] + b[d];
            tup[t * HIDN + d] = v;
            sum += tanhf(v) * aw[d];
        }
        #pragma unroll
        for (int o = 16; o > 0; o >>= 1) sum += __shfl_xor_sync(0xffffffffu, sum, o);
        if (lane == 0) sc[t] = sum;
    }
    __syncthreads();
    if (threadIdx.x == 0) {
        float m = sc[0];
        for (int t = 1; t < T_LEN; t++) m = fmaxf(m, sc[t]);
        float ssum = 0.f;
        for (int t = 0; t < T_LEN; t++) { float e2 = expf(sc[t] - m); sc[t] = e2; ssum += e2; }
        float inv = 1.f / ssum;
        for (int t = 0; t < T_LEN; t++) sc[t] *= inv;
    }
    __syncthreads();
    for (int d = threadIdx.x; d < HIDN; d += 256) {
        float acc = 0.f;
        #pragma unroll 7
        for (int t = 0; t < T_LEN; t++) acc += sc[t] * tup[t * HIDN + d];
        g_H[(size_t)s * HIDN + d] = acc;
    }
}

// ---------------- bag attention + logits + BCE ------------------------------
__global__ void __launch_bounds__(128) bag_kernel(
    const float* __restrict__ sen_a, const float* __restrict__ sen_r,
    const float* __restrict__ rel, const float* __restrict__ sen_d,
    const int* __restrict__ label, float* __restrict__ logits)
{
    const int b = blockIdx.x;
    __shared__ float Hs[NSEN][HIDN];
    __shared__ float ew[NSEN];
    __shared__ float Sv[HIDN];
    __shared__ float red[128];

    for (int e = threadIdx.x; e < NSEN * HIDN; e += 128)
        Hs[e / HIDN][e % HIDN] = g_H[(size_t)b * NSEN * HIDN + e];
    __syncthreads();

    const int lane = threadIdx.x & 31, wid = threadIdx.x >> 5;
    for (int n = wid; n < NSEN; n += 4) {
        float sum = 0.f;
        for (int d = lane; d < HIDN; d += 32)
            sum += Hs[n][d] * sen_a[d] * sen_r[d];
        #pragma unroll
        for (int o = 16; o > 0; o >>= 1) sum += __shfl_xor_sync(0xffffffffu, sum, o);
        if (lane == 0) ew[n] = sum;
    }
    __syncthreads();
    if (threadIdx.x == 0) {
        float m = ew[0];
        for (int n = 1; n < NSEN; n++) m = fmaxf(m, ew[n]);
        float s2 = 0.f;
        for (int n = 0; n < NSEN; n++) { float e2 = expf(ew[n] - m); ew[n] = e2; s2 += e2; }
        float inv = 1.f / s2;
        for (int n = 0; n < NSEN; n++) ew[n] *= inv;
    }
    __syncthreads();
    for (int d = threadIdx.x; d < HIDN; d += 128) {
        float acc = 0.f;
        for (int n = 0; n < NSEN; n++) acc += ew[n] * Hs[n][d];
        Sv[d] = acc;
    }
    __syncthreads();

    int lab = label[b];
    float bce = 0.f;
    if (threadIdx.x < NREL) {
        int r = threadIdx.x;
        float l = sen_d[r];
        for (int d = 0; d < HIDN; d++) l += Sv[d] * rel[(size_t)r * HIDN + d];
        logits[(size_t)b * NREL + r] = l;
        float tgt = (lab == r) ? 1.f : 0.f;
        bce = fmaxf(l, 0.f) - l * tgt + log1pf(expf(-fabsf(l)));
    }
    red[threadIdx.x] = bce;
    __syncthreads();
    for (int o = 64; o > 0; o >>= 1) {
        if (threadIdx.x < o) red[threadIdx.x] += red[threadIdx.x + o];
        __syncthreads();
    }
    if (threadIdx.x == 0) g_bagloss[b] = red[0] / (float)NREL;
}

__global__ void loss_sum_kernel(float* __restrict__ out) {
    __shared__ float red[128];
    red[threadIdx.x] = g_bagloss[threadIdx.x];
    __syncthreads();
    for (int o = 64; o > 0; o >>= 1) {
        if (threadIdx.x < o) red[threadIdx.x] += red[threadIdx.x + o];
        __syncthreads();
    }
    if (threadIdx.x == 0) out[0] = red[0];
}

// ---------------- launch ----------------------------------------------------
extern "C" void kernel_launch(void* const* d_in, const int* in_sizes, int n_in,
                              void* d_out, int out_size)
{
    const int*   tok    = (const int*)d_in[0];
    const int*   p1     = (const int*)d_in[1];
    const int*   p2     = (const int*)d_in[2];
    const int*   lab    = (const int*)d_in[3];
    const float* emb    = (const float*)d_in[4];
    const float* pemb   = (const float*)d_in[5];
    const float* Wih_f  = (const float*)d_in[6];
    const float* Whh_f  = (const float*)d_in[7];
    const float* bih_f  = (const float*)d_in[8];
    const float* bhh_f  = (const float*)d_in[9];
    const float* Wih_b  = (const float*)d_in[10];
    const float* Whh_b  = (const float*)d_in[11];
    const float* bih_b  = (const float*)d_in[12];
    const float* bhh_b  = (const float*)d_in[13];
    const float* aw     = (const float*)d_in[14];
    const float* sen_a  = (const float*)d_in[15];
    const float* sen_r  = (const float*)d_in[16];
    const float* rel    = (const float*)d_in[17];
    const float* sen_d  = (const float*)d_in[18];
    float* out = (float*)d_out;

    init_kernel<<<(S_TOT * HIDN + 255) / 256, 256>>>();
    gather_kernel<<<(S_TOT * T_LEN * IND + 255) / 256, 256>>>(tok, p1, p2, emb, pemb);

    dim3 g2(S_TOT * T_LEN / 256, G3 / 100, 2);
    xp_gemm_kernel<<<g2, 320>>>(Wih_f, Wih_b, bih_f, bih_b);

    static const int gru_smem = HIDN * 96 * 4 + 2 * KCH * 128 * 4;   // 76800+20480
    cudaFuncSetAttribute(gru_persistent_kernel,
                         cudaFuncAttributeMaxDynamicSharedMemorySize, gru_smem);
    dim3 g3(7, 20, 2);
    gru_persistent_kernel<<<g3, 128, gru_smem>>>(Whh_f, Whh_b, bhh_f, bhh_b);

    static const int attn_smem = T_LEN * HIDN * (int)sizeof(float);  // 56000
    cudaFuncSetAttribute(word_attn_kernel,
                         cudaFuncAttributeMaxDynamicSharedMemorySize, attn_smem);
    word_attn_kernel<<<S_TOT, 256, attn_smem>>>(aw);
    bag_kernel<<<NBAG, 128>>>(sen_a, sen_r, rel, sen_d, lab, out + 1);
    loss_sum_kernel<<<1, 128>>>(out);
}